// round 14
// baseline (speedup 1.0000x reference)
#include <cuda_runtime.h>
#include <math.h>

#define BATCH   64
#define MAXN    128
#define GH      64
#define GW      32
#define NPTS    2048        // GH*GW
#define NSPLIT  16
#define MAXCHUNK 8          // ceil(MAXN / NSPLIT)
#define NTHREADS 256
#define PPT     8           // NPTS / NTHREADS
#define TABF4   240         // float4s per triangle table blob (3840 B)

typedef unsigned long long u64;

// Partial accumulators: [BATCH][NSPLIT][NPTS] complex (float2) = 16 MB
__device__ float2 g_partial[BATCH * NSPLIT * NPTS];
// Per-(batch,tri) phasor tables: 8192 x 240 float4 = 30 MB
// blob layout (float4 idx): [0,64) rowQ  [64,128) rowR  [128,160) rowP(f2 x64)
//                           [160,192) colQ [192,224) colR [224,240) colP(f2 x32)
__device__ float4 g_tab[BATCH * MAXN * TABF4];
__device__ float2 g_triAS[BATCH * MAXN];    // (area, scale2)

// ---- packed f32x2 helpers ----
__device__ __forceinline__ u64 pk(float lo, float hi) {
    u64 r; asm("mov.b64 %0, {%1,%2};" : "=l"(r) : "f"(lo), "f"(hi)); return r;
}
__device__ __forceinline__ void upk(u64 v, float& lo, float& hi) {
    asm("mov.b64 {%0,%1}, %2;" : "=f"(lo), "=f"(hi) : "l"(v));
}
__device__ __forceinline__ u64 mul2(u64 a, u64 b) {
    u64 d; asm("mul.rn.f32x2 %0, %1, %2;" : "=l"(d) : "l"(a), "l"(b)); return d;
}
__device__ __forceinline__ u64 fma2(u64 a, u64 b, u64 c) {
    u64 d; asm("fma.rn.f32x2 %0, %1, %2, %3;" : "=l"(d) : "l"(a), "l"(b), "l"(c)); return d;
}
__device__ __forceinline__ u64 add2(u64 a, u64 b) {
    u64 d; asm("add.rn.f32x2 %0, %1, %2;" : "=l"(d) : "l"(a), "l"(b)); return d;
}

// pos_w[k] = 0.1 * 10^(k/30), float path: one MUFU EX2, <=3 ulp.
__device__ __forceinline__ float pos_w_fast(int k) {
    return 0.1f * exp2f((float)k * 0.110730936496245417f);
}
__device__ __forceinline__ float wx_of(int h) {
    if (h < 31)  return -pos_w_fast(30 - h);
    if (h == 31) return 0.0f;
    if (h <= 62) return pos_w_fast(h - 32);
    return 0.0f;                       // padded row
}
__device__ __forceinline__ float wy_of(int w) {
    return (w == 0) ? 0.0f : pos_w_fast(w - 1);
}

#define TWO_PI_F   6.28318530717958648f
#define FOUR_PI2_F (4.0f * 3.14159274101257324f * 3.14159274101257324f)

// ---- table build: one block per (batch, tri) slot, fully parallel sincos ----
__global__ __launch_bounds__(96)
void pfc_build_tables(const float* __restrict__ tris,
                      const int* __restrict__ lengths) {
    const int bt = blockIdx.x;            // 0 .. BATCH*MAXN-1
    const int b  = bt >> 7;
    const int t  = bt & (MAXN - 1);
    if (t >= lengths[b]) return;

    const float* p = tris + (size_t)bt * 6;
    const float xq = p[0], yq = p[1];
    const float xr = p[2], yr = p[3];
    const float xs = p[4], ys = p[5];

    float4* blob = g_tab + (size_t)bt * TABF4;
    const int tid = threadIdx.x;

    if (tid < GH) {
        const int h = tid;
        const float wx = wx_of(h);
        float sq, cq, sr, cr, sp, cp;
        sincosf(-TWO_PI_F * (wx * xq), &sq, &cq);
        sincosf(-TWO_PI_F * (wx * xr), &sr, &cr);
        sincosf(-TWO_PI_F * (wx * xs), &sp, &cp);
        blob[h]      = make_float4(cq, sq, -sq, wx * (xr - xq));
        blob[64 + h] = make_float4(cr, sr, -sr, wx * (xs - xr));
        reinterpret_cast<float2*>(blob + 128)[h] = make_float2(cp, sp);
    } else {
        const int w = tid - GH;
        const float wy = wy_of(w);
        float sq, cq, sr, cr, sp, cp;
        sincosf(-TWO_PI_F * (wy * yq), &sq, &cq);
        sincosf(-TWO_PI_F * (wy * yr), &sr, &cr);
        sincosf(-TWO_PI_F * (wy * ys), &sp, &cp);
        blob[160 + w] = make_float4(cq, sq, wy * (yr - yq), 0.0f);
        blob[192 + w] = make_float4(cr, sr, wy * (ys - yr), 0.0f);
        reinterpret_cast<float2*>(blob + 224)[w] = make_float2(cp, sp);
    }
    if (tid == 0) {
        const float det = xq * (yr - ys) + xr * (ys - yq) + xs * (yq - yr);
        const float area = fabsf(0.5f * det);
        g_triAS[bt] = make_float2(area, 2.0f * area / FOUR_PI2_F);
    }
}

__global__ __launch_bounds__(NTHREADS)
void pfc_accum_kernel(const int* __restrict__ lengths) {
    __shared__ float4 sTab[MAXCHUNK * TABF4];   // 30720 B
    __shared__ float2 sAS[MAXCHUNK];

    const int tid = threadIdx.x;
    const int b   = blockIdx.x >> 4;        // / NSPLIT
    const int s   = blockIdx.x & (NSPLIT - 1);

    const int len  = lengths[b];
    const int ntri = (len > s) ? ((len - 1 - s) / NSPLIT + 1) : 0;

    // ---- load all triangle tables for this block (coalesced LDG.128) ----
    for (int j = 0; j < ntri; j++) {
        const int bt = b * MAXN + s + j * NSPLIT;
        const float4* src = g_tab + (size_t)bt * TABF4;
        float4* dst = sTab + j * TABF4;
        if (tid < TABF4) dst[tid] = src[tid];          // 240 of 256 threads
        if (tid == 255) sAS[j] = g_triAS[bt];
    }
    __syncthreads();                                   // the ONLY barrier

    const int w     = tid & 31;
    const int hbase = (tid >> 5) * PPT;

    u64 acc[PPT];
#pragma unroll
    for (int k = 0; k < PPT; k++) acc[k] = 0ull;

    for (int j = 0; j < ntri; j++) {
        const float4* tab = sTab + j * TABF4;
        // per-triangle column prep (once per thread, reused over 8 h's)
        const float4 cQ = tab[160 + w];
        const float4 cR = tab[192 + w];
        const float2 cS = reinterpret_cast<const float2*>(tab + 224)[w];
        const u64 cQcdN = pk(-cQ.x, -cQ.y);     // negated -> produces -Eq
        const u64 cQdcN = pk(-cQ.y, -cQ.x);
        const u64 cRcd  = pk( cR.x,  cR.y);     // positive -> Er
        const u64 cRdc  = pk( cR.y,  cR.x);
        const u64 cScdN = pk(-cS.x, -cS.y);     // negated -> -Es
        const u64 cSdcN = pk(-cS.y, -cS.x);
        const float cLinU = cQ.z;
        const float cLinV = cR.z;
        const float2 as = sAS[j];
        const float area   = as.x;
        const float scale2 = as.y;

#pragma unroll
        for (int k = 0; k < PPT; k++) {
            const int h = hbase + k;            // uniform across the warp
            const float4 rQ = tab[h];
            const float4 rR = tab[64 + h];
            const float2 rP = reinterpret_cast<const float2*>(tab + 128)[h];

            const float U_ = rQ.w + cLinU;
            const float V_ = rR.w + cLinV;
            const float S  = U_ + V_;

            // vertex phasors (row x col complex product), Q and S negated
            u64 EqN = mul2(pk(rQ.x, rQ.x), cQcdN);
            EqN     = fma2(pk(rQ.z, rQ.y), cQdcN, EqN);
            u64 Er  = mul2(pk(rR.x, rR.x), cRcd);
            Er      = fma2(pk(rR.z, rR.y), cRdc, Er);
            u64 EsN = mul2(pk(rP.x, rP.x), cScdN);
            EsN     = fma2(pk(-rP.y, rP.y), cSdcN, EsN);

            if (U_ != 0.0f && V_ != 0.0f && S != 0.0f) {          // normal
                // p2 = -U_*Es + S*Er - V_*Eq  =  U_*EsN + S*Er + V_*EqN
                u64 p2 = mul2(pk(U_, U_), EsN);
                p2 = fma2(pk(S, S), Er, p2);
                p2 = fma2(pk(V_, V_), EqN, p2);
                const float scale = __fdividef(scale2, U_ * V_ * S);
                acc[k] = fma2(pk(scale, scale), p2, acc[k]);
            } else {
                float eqr, eqi, esr, esi, erre, erim;
                upk(EqN, eqr, eqi); eqr = -eqr; eqi = -eqi;
                upk(EsN, esr, esi); esr = -esr; esi = -esi;
                upk(Er, erre, erim);
                if (U_ == 0.0f && V_ == 0.0f) {                   // zero
                    acc[k] = add2(acc[k], pk(area, 0.0f));
                } else if (S == 0.0f) {                           // diag
                    const float scale = -__fdividef(scale2, U_ * U_);
                    const float wim = TWO_PI_F * U_;
                    const float tre = erre - eqr - wim * eqi;
                    const float tim = erim - eqi + wim * eqr;
                    acc[k] = fma2(pk(scale, scale), pk(tre, tim), acc[k]);
                } else if (U_ == 0.0f) {                          // u-mask
                    const float scale = -__fdividef(scale2, V_ * V_);
                    const float wim = TWO_PI_F * V_;
                    const float tre = esr - eqr - wim * eqi;
                    const float tim = esi - eqi + wim * eqr;
                    acc[k] = fma2(pk(scale, scale), pk(tre, tim), acc[k]);
                } else {                                          // v-mask
                    const float scale = __fdividef(scale2, U_ * U_);
                    const float wim = TWO_PI_F * U_;
                    const float tre = erre - wim * erim - eqr;
                    const float tim = erim + wim * erre - eqi;
                    acc[k] = fma2(pk(scale, scale), pk(tre, tim), acc[k]);
                }
            }
        }
    }

#pragma unroll
    for (int k = 0; k < PPT; k++) {
        const int p = (hbase + k) * GW + w;
        *reinterpret_cast<u64*>(&g_partial[(b * NSPLIT + s) * NPTS + p]) = acc[k];
    }
}

// Two threads per point: each sums 8 of the 16 stages, exchange via smem,
// then half-0 writes mag and half-1 writes phase.
__global__ __launch_bounds__(256)
void pfc_finalize_kernel(float* __restrict__ out) {
    __shared__ float2 sPart[256];
    const int tid  = threadIdx.x;
    const int lp   = tid & 127;               // local point
    const int half = tid >> 7;                // 0: stages 0-7, 1: stages 8-15
    const int idx  = blockIdx.x * 128 + lp;   // 0 .. BATCH*NPTS-1
    const int b = idx / NPTS;
    const int p = idx % NPTS;
    const int h = p >> 5;

    float re = 0.0f, im = 0.0f;
    const int sbase = half * 8;
#pragma unroll
    for (int s = 0; s < 8; s++) {
        float2 v = g_partial[(b * NSPLIT + sbase + s) * NPTS + p];
        re += v.x; im += v.y;
    }
    sPart[tid] = make_float2(re, im);
    __syncthreads();
    const float2 o = sPart[tid ^ 128];
    if (half == 0) { re = re + o.x; im = im + o.y; }
    else           { re = o.x + re; im = o.y + im; }

    const float m2 = re * re + im * im;
    const bool nul = (h == GH - 1) || (m2 == 0.0f);   // padded row or zero
    if (half == 0) {
        out[idx] = nul ? 0.0f : log1pf(sqrtf(m2));                  // mag
    } else {
        out[BATCH * NPTS + idx] = nul ? 0.0f : atan2f(im, re);      // phase
    }
}

extern "C" void kernel_launch(void* const* d_in, const int* in_sizes, int n_in,
                              void* d_out, int out_size) {
    const float* tris    = (const float*)d_in[0];   // [64,128,3,2] f32
    const int*   lengths = (const int*)d_in[1];     // [64] i32
    float* out = (float*)d_out;                     // 262144 f32: mag then phase

    pfc_build_tables<<<BATCH * MAXN, 96>>>(tris, lengths);
    pfc_accum_kernel<<<BATCH * NSPLIT, NTHREADS>>>(lengths);
    pfc_finalize_kernel<<<(BATCH * NPTS) / 128, 256>>>(out);
}